// round 14
// baseline (speedup 1.0000x reference)
#include <cuda_runtime.h>
#include <math.h>

#define DD 1024
#define BB 64
#define NCHUNK 2048
#define ID_ACT  2048
#define ID_SV   2112
#define ID_SEV  2144
#define ID_CONF 2208
#define NIDS    2720

// ---------------- device scratch (no allocations allowed) ----------------
__device__ float g_part[BB * 32 * DD];       // per-chunk partials (8MB)
__device__ float g_action[BB * DD];
__device__ float g_basec[512];
__device__ float g_svctx[256];
__device__ float g_norm_w[64];
__device__ float g_proto_part[2][64 * 512];
__device__ float g_act_part[8][64 * 512];
__device__ float g_svh_part[8][64 * 256];
__device__ float g_wcp[BB * 8];
__device__ float g_sev[BB];
__device__ unsigned int g_bdone[BB];         // per-batch chunk tickets
__device__ unsigned int g_done[BB];          // per-batch output tickets (9)
__device__ unsigned int g_ctr;               // work-stealing counter
__device__ unsigned int g_cdone;             // collapses done (64)
__device__ unsigned int g_adone;             // act gemm units done (64)
__device__ unsigned int g_sdone;             // sv gemm units done (32)
__device__ unsigned int g_pdone;             // proto prologue blocks done (16)
__device__ unsigned int g_chain;             // chain done flag

__device__ __forceinline__ float gelu_f(float x) {
    return 0.5f * x * (1.0f + erff(x * 0.70710678118654752440f));
}
__device__ __forceinline__ float sigmoid_f(float x) {
    return 1.0f / (1.0f + expf(-x));
}
__device__ __forceinline__ void bar_group(int id) {
    asm volatile("bar.sync %0, 256;" :: "r"(id) : "memory");
}
__device__ __forceinline__ void wait_ge(unsigned int* cnt, unsigned int tgt,
                                        int gtid, int barid) {
    if (gtid == 0) {
        while (atomicAdd(cnt, 0u) < tgt) __nanosleep(256);
    }
    bar_group(barid);
    __threadfence();
}

__device__ void assemble_out(int b, float* __restrict__ out) {
    float wc = 0.f;
#pragma unroll
    for (int j = 0; j < 8; j++) wc += ((volatile float*)g_wcp)[b * 8 + j];
    float sev = ((volatile float*)g_sev)[b];
    float viol = 1.0f - wc;
    out[64 + b]  = wc;
    out[128 + b] = viol;
    out[192 + b] = sev;
    out[b]       = viol * sev * 0.1f;
}

// ---- k-split GEMV, float4 weights, 1024 threads ---------------------------
template <int N, int K>
__device__ __forceinline__ void gemv_f4(const float* __restrict__ in,
                                        const float* __restrict__ W,
                                        float* __restrict__ red, int tid)
{
    constexpr int NJ4 = N / 4;
    constexpr int KS = 1024 / NJ4;
    constexpr int KN = K / KS;
    int c = tid / NJ4;
    int j4 = tid % NJ4;
    const float4* Wp = (const float4*)W + j4;
    int i0 = c * KN;
    float4 acc = make_float4(0.f, 0.f, 0.f, 0.f);
#pragma unroll 4
    for (int i = 0; i < KN; i++) {
        float s = in[i0 + i];
        float4 w = Wp[(size_t)(i0 + i) * NJ4];
        acc.x += s * w.x; acc.y += s * w.y; acc.z += s * w.z; acc.w += s * w.w;
    }
    ((float4*)red)[c * NJ4 + j4] = acc;
}

// ---- full-block 64x64 GEMM (proto prologue only) --------------------------
__device__ __forceinline__ void gemm64(const float* __restrict__ Ag,
                                       const float* __restrict__ W, int N,
                                       int nt, int k0, int Kb,
                                       float* __restrict__ Cp, float* sm)
{
    float* As = sm;               // [64][33]
    float* Ws = sm + 64 * 33;     // [32][64]
    int tid = threadIdx.x;
    bool act = (tid < 256);
    int tx = tid & 15;
    int ty = (tid >> 4) & 15;
    float acc[4][4];
#pragma unroll
    for (int r = 0; r < 4; r++)
#pragma unroll
        for (int c = 0; c < 4; c++) acc[r][c] = 0.f;

    for (int kb = 0; kb < Kb; kb += 32) {
        int kbase = k0 + kb;
        if (act) {
            for (int e = tid; e < 64 * 32; e += 256) {
                int m = e >> 5, kk = e & 31;
                As[m * 33 + kk] = Ag[(size_t)m * DD + kbase + kk];
            }
            for (int e = tid; e < 32 * 64; e += 256) {
                int kk = e >> 6, n = e & 63;
                Ws[kk * 64 + n] = W[(size_t)(kbase + kk) * N + nt * 64 + n];
            }
        }
        __syncthreads();
        if (act) {
#pragma unroll
            for (int kk = 0; kk < 32; kk++) {
                float4 wf = *(const float4*)&Ws[kk * 64 + tx * 4];
                float a0 = As[(ty * 4 + 0) * 33 + kk];
                float a1 = As[(ty * 4 + 1) * 33 + kk];
                float a2 = As[(ty * 4 + 2) * 33 + kk];
                float a3 = As[(ty * 4 + 3) * 33 + kk];
                acc[0][0] += a0 * wf.x; acc[0][1] += a0 * wf.y; acc[0][2] += a0 * wf.z; acc[0][3] += a0 * wf.w;
                acc[1][0] += a1 * wf.x; acc[1][1] += a1 * wf.y; acc[1][2] += a1 * wf.z; acc[1][3] += a1 * wf.w;
                acc[2][0] += a2 * wf.x; acc[2][1] += a2 * wf.y; acc[2][2] += a2 * wf.z; acc[2][3] += a2 * wf.w;
                acc[3][0] += a3 * wf.x; acc[3][1] += a3 * wf.y; acc[3][2] += a3 * wf.z; acc[3][3] += a3 * wf.w;
            }
        }
        __syncthreads();
    }
    if (act) {
#pragma unroll
        for (int r = 0; r < 4; r++) {
            float4 v = make_float4(acc[r][0], acc[r][1], acc[r][2], acc[r][3]);
            *(float4*)&Cp[(size_t)(ty * 4 + r) * N + nt * 64 + tx * 4] = v;
        }
    }
}

// ---- group-scoped 64x64 GEMM, K=128 per unit, 16-k chunks -----------------
__device__ __forceinline__ void gemm64g(const float* __restrict__ Ag,
                                        const float* __restrict__ W, int N,
                                        int nt, int k0,
                                        float* __restrict__ Cp,
                                        float* smg, int gtid, int barid)
{
    float* As = smg;              // 64*17 = 1088
    float* Ws = smg + 1088;       // 16*64 = 1024
    int tx = gtid & 15;
    int ty = gtid >> 4;
    float acc[4][4];
#pragma unroll
    for (int r = 0; r < 4; r++)
#pragma unroll
        for (int c = 0; c < 4; c++) acc[r][c] = 0.f;

    for (int kb = 0; kb < 128; kb += 16) {
        int kbase = k0 + kb;
        for (int e = gtid; e < 1024; e += 256) {
            int m = e >> 4, kk = e & 15;
            As[m * 17 + kk] = Ag[(size_t)m * DD + kbase + kk];
        }
        for (int e = gtid; e < 1024; e += 256) {
            int kk = e >> 6, n = e & 63;
            Ws[kk * 64 + n] = W[(size_t)(kbase + kk) * N + nt * 64 + n];
        }
        bar_group(barid);
#pragma unroll
        for (int kk = 0; kk < 16; kk++) {
            float4 wf = *(const float4*)&Ws[kk * 64 + tx * 4];
            float a0 = As[(ty * 4 + 0) * 17 + kk];
            float a1 = As[(ty * 4 + 1) * 17 + kk];
            float a2 = As[(ty * 4 + 2) * 17 + kk];
            float a3 = As[(ty * 4 + 3) * 17 + kk];
            acc[0][0] += a0 * wf.x; acc[0][1] += a0 * wf.y; acc[0][2] += a0 * wf.z; acc[0][3] += a0 * wf.w;
            acc[1][0] += a1 * wf.x; acc[1][1] += a1 * wf.y; acc[1][2] += a1 * wf.z; acc[1][3] += a1 * wf.w;
            acc[2][0] += a2 * wf.x; acc[2][1] += a2 * wf.y; acc[2][2] += a2 * wf.z; acc[2][3] += a2 * wf.w;
            acc[3][0] += a3 * wf.x; acc[3][1] += a3 * wf.y; acc[3][2] += a3 * wf.z; acc[3][3] += a3 * wf.w;
        }
        bar_group(barid);
    }
#pragma unroll
    for (int r = 0; r < 4; r++) {
        float4 v = make_float4(acc[r][0], acc[r][1], acc[r][2], acc[r][3]);
        *(float4*)&Cp[(size_t)(ty * 4 + r) * N + nt * 64 + tx * 4] = v;
    }
}

// ---- the batch-invariant ctx chain (block 0, 1024 threads) ----------------
__device__ void run_chain(const float* __restrict__ cb,
                          const float* __restrict__ ce_w1, const float* __restrict__ ce_b1,
                          const float* __restrict__ ce_w2, const float* __restrict__ ce_b2,
                          const float* __restrict__ rms_w,
                          const float* __restrict__ nm_w1,
                          const float* __restrict__ ns_w1, const float* __restrict__ ns_b1,
                          const float* __restrict__ ns_w2, const float* __restrict__ ns_b2,
                          const float* __restrict__ sv_w1,
                          float* sm, int tid)
{
    float* sc  = sm;           // 1024
    float* red = sm + 1024;    // 4096
    float* sh  = sm + 5120;    // 256
    float* slg = sm + 5376;    // 64

    if (tid < 256) {
        const float4* cbp = (const float4*)cb + tid;
        float4 a = make_float4(0.f, 0.f, 0.f, 0.f);
#pragma unroll
        for (int r = 0; r < 16; r++) {
            float4 v = cbp[r * 256];
            a.x += v.x; a.y += v.y; a.z += v.z; a.w += v.w;
        }
        const float s = 1.0f / 16.0f;
        a.x *= s; a.y *= s; a.z *= s; a.w *= s;
        ((float4*)sc)[tid] = a;
    }
    __syncthreads();

    gemv_f4<256, 1024>(sc, ce_w1, red, tid);
    __syncthreads();
    if (tid < 256) {
        float a = ce_b1[tid];
#pragma unroll
        for (int c = 0; c < 16; c++) a += red[c * 256 + tid];
        sh[tid] = gelu_f(a);
    }
    __syncthreads();

    gemv_f4<1024, 256>(sh, ce_w2, red, tid);
    __syncthreads();
    float4 e4;
    if (tid < 256) {
        float4 p0 = ((float4*)red)[tid];
        float4 p1 = ((float4*)red)[256 + tid];
        float4 p2 = ((float4*)red)[512 + tid];
        float4 p3 = ((float4*)red)[768 + tid];
        float4 bb = ((const float4*)ce_b2)[tid];
        e4.x = p0.x + p1.x + p2.x + p3.x + bb.x;
        e4.y = p0.y + p1.y + p2.y + p3.y + bb.y;
        e4.z = p0.z + p1.z + p2.z + p3.z + bb.z;
        e4.w = p0.w + p1.w + p2.w + p3.w + bb.w;
    }
    __syncthreads();
    if (tid < 256)
        red[tid] = e4.x * e4.x + e4.y * e4.y + e4.z * e4.z + e4.w * e4.w;
    __syncthreads();
    for (int s2 = 128; s2 > 0; s2 >>= 1) {
        if (tid < s2) red[tid] += red[tid + s2];
        __syncthreads();
    }
    if (tid < 256) {
        float inv = rsqrtf(red[0] * (1.0f / 1024.0f) + 1e-6f);
        float4 rw = ((const float4*)rms_w)[tid];
        float4 ce;
        ce.x = e4.x * inv * rw.x; ce.y = e4.y * inv * rw.y;
        ce.z = e4.z * inv * rw.z; ce.w = e4.w * inv * rw.w;
        ((float4*)sc)[tid] = ce;
    }
    __syncthreads();

    gemv_f4<256, 1024>(sc, ns_w1, red, tid);
    __syncthreads();
    if (tid < 256) {
        float a = ns_b1[tid];
#pragma unroll
        for (int c = 0; c < 16; c++) a += red[c * 256 + tid];
        sh[tid] = gelu_f(a);
    }
    __syncthreads();

    gemv_f4<64, 256>(sh, ns_w2, red, tid);
    __syncthreads();
    if (tid < 64) {
        float a = ns_b2[tid];
#pragma unroll
        for (int c = 0; c < 64; c++) a += red[c * 64 + tid];
        slg[tid] = a;
    }
    __syncthreads();
    if (tid < 64) {
        float m = -1e30f;
        for (int k = 0; k < 64; k++) m = fmaxf(m, slg[k]);
        float s = 0.f;
        for (int k = 0; k < 64; k++) s += expf(slg[k] - m);
        g_norm_w[tid] = expf(slg[tid] - m) / s;
    }

    gemv_f4<256, 1024>(sc, sv_w1, red, tid);
    __syncthreads();
    if (tid < 256) {
        float a = 0.f;
#pragma unroll
        for (int c = 0; c < 16; c++) a += red[c * 256 + tid];
        g_svctx[tid] = a;
    }
    __syncthreads();

    gemv_f4<512, 1024>(sc, nm_w1, red, tid);
    __syncthreads();
    if (tid < 512) {
        float a = 0.f;
#pragma unroll
        for (int c = 0; c < 8; c++) a += red[c * 512 + tid];
        g_basec[tid] = a;
    }
    __syncthreads();
}

// ======== k_main: the whole pipeline, persistent + dependency-stealing =====
__global__ __launch_bounds__(1024, 1)
void k_main(const float* __restrict__ x, const float* __restrict__ cb,
            const float* __restrict__ proto,
            const float* __restrict__ ce_w1, const float* __restrict__ ce_b1,
            const float* __restrict__ ce_w2, const float* __restrict__ ce_b2,
            const float* __restrict__ rms_w,
            const float* __restrict__ nm_w1, const float* __restrict__ nm_b1,
            const float* __restrict__ nm_w2, const float* __restrict__ nm_b2,
            const float* __restrict__ ns_w1, const float* __restrict__ ns_b1,
            const float* __restrict__ ns_w2, const float* __restrict__ ns_b2,
            const float* __restrict__ sv_w1, const float* __restrict__ sv_b1,
            const float* __restrict__ sv_w2, const float* __restrict__ sv_b2,
            float* __restrict__ out)
{
    __shared__ __align__(16) float sm[8448];
    __shared__ int s_c[4][2];
    __shared__ int s_flag[4];
    int tid = threadIdx.x;
    int blk = blockIdx.x;

    // ---------------- prologue work on dedicated blocks --------------------
    if (blk == 0) {
        run_chain(cb, ce_w1, ce_b1, ce_w2, ce_b2, rms_w, nm_w1,
                  ns_w1, ns_b1, ns_w2, ns_b2, sv_w1, sm, tid);
        __threadfence();
        __syncthreads();
        if (tid == 0) atomicExch(&g_chain, 1u);
    } else if (blk <= 16) {
        int pi = blk - 1;
        int nt = pi & 7, ks = pi >> 3;
        gemm64(proto, nm_w1 + (size_t)2048 * 512, 512, nt, ks * 512, 512,
               g_proto_part[ks], sm);
        __threadfence();
        __syncthreads();
        if (tid == 0) atomicAdd(&g_pdone, 1u);
    }

    // ---------------- dependency-tracked group stealing ---------------------
    int gid = tid >> 8;
    int gtid = tid & 255;
    int barid = gid + 1;
    float* smg = sm + gid * 2112;
    const float inv_t = 1.0f / 2048.0f;

    if (gtid == 0) s_c[gid][0] = (int)atomicAdd(&g_ctr, 1u);
    bar_group(barid);
    int p = 0;
    for (;;) {
        int c = s_c[gid][p];
        if (gtid == 0) s_c[gid][p ^ 1] = (int)atomicAdd(&g_ctr, 1u);
        if (c >= NIDS) break;

        if (c < NCHUNK) {
            // -------- reduce chunk: 64 rows, this thread owns one quad -----
            int b = c >> 5, s = c & 31;
            const float4* xp = (const float4*)x
                             + ((size_t)b * 2048 + s * 64) * 256 + gtid;
            float4 a = make_float4(0.f, 0.f, 0.f, 0.f);
#pragma unroll 8
            for (int t = 0; t < 64; t++) {
                float4 v = __ldcs(xp + (size_t)t * 256);
                a.x += v.x; a.y += v.y; a.z += v.z; a.w += v.w;
            }
            a.x *= inv_t; a.y *= inv_t; a.z *= inv_t; a.w *= inv_t;
            ((float4*)g_part)[(size_t)(b * 32 + s) * 256 + gtid] = a;
            __threadfence();
            bar_group(barid);
            if (gtid == 0) {
                unsigned int old = atomicAdd(&g_bdone[b], 1u);
                s_flag[gid] = (old == 31u);
            }
            bar_group(barid);
            if (s_flag[gid]) {
                // inline collapse for batch b (fixed slab order)
                const float4* pp = (const float4*)g_part
                                 + (size_t)b * 32 * 256 + gtid;
                float4 aa = make_float4(0.f, 0.f, 0.f, 0.f);
#pragma unroll 8
                for (int sl = 0; sl < 32; sl++) {
                    float4 v = pp[(size_t)sl * 256];
                    aa.x += v.x; aa.y += v.y; aa.z += v.z; aa.w += v.w;
                }
                ((float4*)g_action)[b * 256 + gtid] = aa;
                __threadfence();
                bar_group(barid);
                if (gtid == 0) atomicAdd(&g_cdone, 1u);
            }
        } else if (c < ID_SV) {
            // -------- act GEMM unit ----------------------------------------
            wait_ge(&g_cdone, 64u, gtid, barid);
            int u = c - ID_ACT;
            int nt = u & 7, ks = u >> 3;
            gemm64g(g_action, nm_w1 + (size_t)1024 * 512, 512, nt, ks * 128,
                    g_act_part[ks], smg, gtid, barid);
            __threadfence();
            bar_group(barid);
            if (gtid == 0) atomicAdd(&g_adone, 1u);
        } else if (c < ID_SEV) {
            // -------- sv GEMM unit -----------------------------------------
            wait_ge(&g_cdone, 64u, gtid, barid);
            int u = c - ID_SV;
            int nt = u & 3, ks = u >> 2;
            gemm64g(g_action, sv_w1 + (size_t)1024 * 256, 256, nt, ks * 128,
                    g_svh_part[ks], smg, gtid, barid);
            __threadfence();
            bar_group(barid);
            if (gtid == 0) atomicAdd(&g_sdone, 1u);
        } else if (c < ID_CONF) {
            // -------- severity for batch b ---------------------------------
            int b = c - ID_SEV;
            wait_ge(&g_sdone, 32u, gtid, barid);
            wait_ge(&g_chain, 1u, gtid, barid);
            float* sred = smg;
            if (gtid < 64) {
                float4 a;
                {
                    float4 sc4 = ((const float4*)g_svctx)[gtid];
                    float4 sb = ((const float4*)sv_b1)[gtid];
                    a.x = sc4.x + sb.x; a.y = sc4.y + sb.y;
                    a.z = sc4.z + sb.z; a.w = sc4.w + sb.w;
                }
#pragma unroll
                for (int pp = 0; pp < 8; pp++) {
                    float4 v = *((const float4*)(g_svh_part[pp] + b * 256) + gtid);
                    a.x += v.x; a.y += v.y; a.z += v.z; a.w += v.w;
                }
                float4 w = ((const float4*)sv_w2)[gtid];
                sred[gtid] = gelu_f(a.x) * w.x + gelu_f(a.y) * w.y
                           + gelu_f(a.z) * w.z + gelu_f(a.w) * w.w;
            }
            bar_group(barid);
            if (gtid < 32) {
                float a = sred[gtid] + sred[gtid + 32];
#pragma unroll
                for (int o = 16; o > 0; o >>= 1)
                    a += __shfl_down_sync(0xffffffffu, a, o);
                if (gtid == 0) {
                    g_sev[b] = sigmoid_f(a + sv_b2[0]);
                    __threadfence();
                    unsigned int old = atomicAdd(&g_done[b], 1u);
                    if (old == 8u) { __threadfence(); assemble_out(b, out); }
                }
            }
        } else {
            // -------- conf unit (b, kg): 8 k's, one per warp ---------------
            int u = c - ID_CONF;
            int b = u >> 3, kg = u & 7;
            wait_ge(&g_adone, 64u, gtid, barid);
            wait_ge(&g_chain, 1u, gtid, barid);
            wait_ge(&g_pdone, 16u, gtid, barid);
            float* s = smg;              // 512
            float* w2s = smg + 512;      // 512
            float* sconf = smg + 1024;   // 8
            if (gtid < 128) {
                float4 a;
                {
                    float4 bc = ((const float4*)g_basec)[gtid];
                    float4 nb = ((const float4*)nm_b1)[gtid];
                    a.x = bc.x + nb.x; a.y = bc.y + nb.y;
                    a.z = bc.z + nb.z; a.w = bc.w + nb.w;
                }
#pragma unroll
                for (int pp = 0; pp < 8; pp++) {
                    float4 v = *((const float4*)(g_act_part[pp] + b * 512) + gtid);
                    a.x += v.x; a.y += v.y; a.z += v.z; a.w += v.w;
                }
                ((float4*)s)[gtid] = a;
                ((float4*)w2s)[gtid] = ((const float4*)nm_w2)[gtid];
            }
            bar_group(barid);
            int warp = gtid >> 5, lane = gtid & 31;
            int k = kg * 8 + warp;
            const float* p0 = g_proto_part[0] + k * 512;
            const float* p1 = g_proto_part[1] + k * 512;
            float acc0 = 0.f, acc1 = 0.f;
#pragma unroll
            for (int i = 0; i < 8; i++) {
                int h = lane + i * 32;
                int h2 = h + 256;
                acc0 += gelu_f(s[h] + p0[h] + p1[h]) * w2s[h];
                acc1 += gelu_f(s[h2] + p0[h2] + p1[h2]) * w2s[h2];
            }
            float acc = acc0 + acc1;
#pragma unroll
            for (int o = 16; o > 0; o >>= 1)
                acc += __shfl_down_sync(0xffffffffu, acc, o);
            if (lane == 0) sconf[warp] = sigmoid_f(acc + nm_b2[0]) * g_norm_w[k];
            bar_group(barid);
            if (gtid == 0) {
                float partial = 0.f;
#pragma unroll
                for (int w = 0; w < 8; w++) partial += sconf[w];
                g_wcp[b * 8 + kg] = partial;
                __threadfence();
                unsigned int old = atomicAdd(&g_done[b], 1u);
                if (old == 8u) { __threadfence(); assemble_out(b, out); }
            }
        }
        p ^= 1;
        bar_group(barid);
    }
}

// ---- k_reset: re-zero all scheduling state for the next graph replay ------
__global__ void k_reset()
{
    int t = threadIdx.x;
    if (t < 64) { g_bdone[t] = 0u; g_done[t] = 0u; }
    if (t == 64) g_ctr = 0u;
    if (t == 65) g_cdone = 0u;
    if (t == 66) g_adone = 0u;
    if (t == 67) g_sdone = 0u;
    if (t == 68) g_pdone = 0u;
    if (t == 69) g_chain = 0u;
}

extern "C" void kernel_launch(void* const* d_in, const int* in_sizes, int n_in,
                              void* d_out, int out_size) {
    const float* x      = (const float*)d_in[0];
    const float* cb     = (const float*)d_in[1];
    const float* proto  = (const float*)d_in[2];
    const float* ce_w1  = (const float*)d_in[3];
    const float* ce_b1  = (const float*)d_in[4];
    const float* ce_w2  = (const float*)d_in[5];
    const float* ce_b2  = (const float*)d_in[6];
    const float* rms_w  = (const float*)d_in[7];
    const float* nm_w1  = (const float*)d_in[8];
    const float* nm_b1  = (const float*)d_in[9];
    const float* nm_w2  = (const float*)d_in[10];
    const float* nm_b2  = (const float*)d_in[11];
    const float* ns_w1  = (const float*)d_in[12];
    const float* ns_b1  = (const float*)d_in[13];
    const float* ns_w2  = (const float*)d_in[14];
    const float* ns_b2  = (const float*)d_in[15];
    const float* sv_w1  = (const float*)d_in[16];
    const float* sv_b1  = (const float*)d_in[17];
    const float* sv_w2  = (const float*)d_in[18];
    const float* sv_b2  = (const float*)d_in[19];
    float* out = (float*)d_out;

    k_main<<<148, 1024>>>(x, cb, proto, ce_w1, ce_b1, ce_w2, ce_b2, rms_w,
                          nm_w1, nm_b1, nm_w2, nm_b2,
                          ns_w1, ns_b1, ns_w2, ns_b2,
                          sv_w1, sv_b1, sv_w2, sv_b2, out);
    k_reset<<<1, 128>>>();
}

// round 15
// speedup vs baseline: 1.2214x; 1.2214x over previous
#include <cuda_runtime.h>
#include <math.h>

#define DD 1024
#define BB 64
#define NCHUNK 2048          // 64 batches x 32 chunks of 64 t-rows

// ---------------- device scratch (no allocations allowed) ----------------
__device__ float g_part[BB * 32 * DD];       // per-chunk partials (8MB)
__device__ float g_action[BB * DD];          // collapsed action means
__device__ float g_basec[512];
__device__ float g_svctx[256];
__device__ float g_norm_w[64];
__device__ float g_proto_part[2][64 * 512];
__device__ float g_proto[64 * 512];          // merged proto transform
__device__ float g_act_part[8][64 * 512];
__device__ float g_svh_part[8][64 * 256];
__device__ float g_wcp[BB * 8];              // weighted-conf partials per (b,kg)
__device__ float g_sev[BB];                  // severity per b
__device__ unsigned int g_done[BB];          // output tickets (9 per batch)
__device__ unsigned int g_ctr;               // work-stealing counter

__device__ __forceinline__ float gelu_f(float x) {
    return 0.5f * x * (1.0f + erff(x * 0.70710678118654752440f));
}
__device__ __forceinline__ float sigmoid_f(float x) {
    return 1.0f / (1.0f + expf(-x));
}
__device__ __forceinline__ void bar_group(int id) {
    asm volatile("bar.sync %0, 256;" :: "r"(id) : "memory");
}

// ---- k-split GEMV, float4 weights, 1024 threads: in[K](smem) @ W[K x N] ----
template <int N, int K>
__device__ __forceinline__ void gemv_f4(const float* __restrict__ in,
                                        const float* __restrict__ W,
                                        float* __restrict__ red, int tid)
{
    constexpr int NJ4 = N / 4;
    constexpr int KS = 1024 / NJ4;
    constexpr int KN = K / KS;
    int c = tid / NJ4;
    int j4 = tid % NJ4;
    const float4* Wp = (const float4*)W + j4;
    int i0 = c * KN;
    float4 acc = make_float4(0.f, 0.f, 0.f, 0.f);
#pragma unroll 4
    for (int i = 0; i < KN; i++) {
        float s = in[i0 + i];
        float4 w = Wp[(size_t)(i0 + i) * NJ4];
        acc.x += s * w.x; acc.y += s * w.y; acc.z += s * w.z; acc.w += s * w.w;
    }
    ((float4*)red)[c * NJ4 + j4] = acc;
}

// ---------------- register-tiled 64x64 GEMM slice -------------------------
__device__ __forceinline__ void gemm64(const float* __restrict__ Ag,
                                       const float* __restrict__ W, int N,
                                       int nt, int k0, int Kb,
                                       float* __restrict__ Cp, float* sm)
{
    float* As = sm;               // [64][33]
    float* Ws = sm + 64 * 33;     // [32][64]
    int tid = threadIdx.x;
    bool act = (tid < 256);
    int tx = tid & 15;
    int ty = (tid >> 4) & 15;
    float acc[4][4];
#pragma unroll
    for (int r = 0; r < 4; r++)
#pragma unroll
        for (int c = 0; c < 4; c++) acc[r][c] = 0.f;

    for (int kb = 0; kb < Kb; kb += 32) {
        int kbase = k0 + kb;
        if (act) {
            for (int e = tid; e < 64 * 32; e += 256) {
                int m = e >> 5, kk = e & 31;
                As[m * 33 + kk] = Ag[(size_t)m * DD + kbase + kk];
            }
            for (int e = tid; e < 32 * 64; e += 256) {
                int kk = e >> 6, n = e & 63;
                Ws[kk * 64 + n] = W[(size_t)(kbase + kk) * N + nt * 64 + n];
            }
        }
        __syncthreads();
        if (act) {
#pragma unroll
            for (int kk = 0; kk < 32; kk++) {
                float4 wf = *(const float4*)&Ws[kk * 64 + tx * 4];
                float a0 = As[(ty * 4 + 0) * 33 + kk];
                float a1 = As[(ty * 4 + 1) * 33 + kk];
                float a2 = As[(ty * 4 + 2) * 33 + kk];
                float a3 = As[(ty * 4 + 3) * 33 + kk];
                acc[0][0] += a0 * wf.x; acc[0][1] += a0 * wf.y; acc[0][2] += a0 * wf.z; acc[0][3] += a0 * wf.w;
                acc[1][0] += a1 * wf.x; acc[1][1] += a1 * wf.y; acc[1][2] += a1 * wf.z; acc[1][3] += a1 * wf.w;
                acc[2][0] += a2 * wf.x; acc[2][1] += a2 * wf.y; acc[2][2] += a2 * wf.z; acc[2][3] += a2 * wf.w;
                acc[3][0] += a3 * wf.x; acc[3][1] += a3 * wf.y; acc[3][2] += a3 * wf.z; acc[3][3] += a3 * wf.w;
            }
        }
        __syncthreads();
    }
    if (act) {
#pragma unroll
        for (int r = 0; r < 4; r++) {
            float4 v = make_float4(acc[r][0], acc[r][1], acc[r][2], acc[r][3]);
            *(float4*)&Cp[(size_t)(ty * 4 + r) * N + nt * 64 + tx * 4] = v;
        }
    }
}

// ---- the batch-invariant ctx chain (block 0 only, 1024 threads) ----------
__device__ void run_chain(const float* __restrict__ cb,
                          const float* __restrict__ ce_w1, const float* __restrict__ ce_b1,
                          const float* __restrict__ ce_w2, const float* __restrict__ ce_b2,
                          const float* __restrict__ rms_w,
                          const float* __restrict__ nm_w1,
                          const float* __restrict__ ns_w1, const float* __restrict__ ns_b1,
                          const float* __restrict__ ns_w2, const float* __restrict__ ns_b2,
                          const float* __restrict__ sv_w1,
                          float* sm, int tid)
{
    float* sc  = sm;           // 1024: ctx, then ctx_enc
    float* red = sm + 1024;    // 4096
    float* sh  = sm + 5120;    // 256
    float* slg = sm + 5376;    // 64

    if (tid < 256) {
        const float4* cbp = (const float4*)cb + tid;
        float4 a = make_float4(0.f, 0.f, 0.f, 0.f);
#pragma unroll
        for (int r = 0; r < 16; r++) {
            float4 v = cbp[r * 256];
            a.x += v.x; a.y += v.y; a.z += v.z; a.w += v.w;
        }
        const float s = 1.0f / 16.0f;
        a.x *= s; a.y *= s; a.z *= s; a.w *= s;
        ((float4*)sc)[tid] = a;
    }
    __syncthreads();

    gemv_f4<256, 1024>(sc, ce_w1, red, tid);
    __syncthreads();
    if (tid < 256) {
        float a = ce_b1[tid];
#pragma unroll
        for (int c = 0; c < 16; c++) a += red[c * 256 + tid];
        sh[tid] = gelu_f(a);
    }
    __syncthreads();

    gemv_f4<1024, 256>(sh, ce_w2, red, tid);
    __syncthreads();
    float4 e4;
    if (tid < 256) {
        float4 p0 = ((float4*)red)[tid];
        float4 p1 = ((float4*)red)[256 + tid];
        float4 p2 = ((float4*)red)[512 + tid];
        float4 p3 = ((float4*)red)[768 + tid];
        float4 bb = ((const float4*)ce_b2)[tid];
        e4.x = p0.x + p1.x + p2.x + p3.x + bb.x;
        e4.y = p0.y + p1.y + p2.y + p3.y + bb.y;
        e4.z = p0.z + p1.z + p2.z + p3.z + bb.z;
        e4.w = p0.w + p1.w + p2.w + p3.w + bb.w;
    }
    __syncthreads();
    if (tid < 256)
        red[tid] = e4.x * e4.x + e4.y * e4.y + e4.z * e4.z + e4.w * e4.w;
    __syncthreads();
    for (int s2 = 128; s2 > 0; s2 >>= 1) {
        if (tid < s2) red[tid] += red[tid + s2];
        __syncthreads();
    }
    if (tid < 256) {
        float inv = rsqrtf(red[0] * (1.0f / 1024.0f) + 1e-6f);
        float4 rw = ((const float4*)rms_w)[tid];
        float4 ce;
        ce.x = e4.x * inv * rw.x; ce.y = e4.y * inv * rw.y;
        ce.z = e4.z * inv * rw.z; ce.w = e4.w * inv * rw.w;
        ((float4*)sc)[tid] = ce;
    }
    __syncthreads();

    gemv_f4<256, 1024>(sc, ns_w1, red, tid);
    __syncthreads();
    if (tid < 256) {
        float a = ns_b1[tid];
#pragma unroll
        for (int c = 0; c < 16; c++) a += red[c * 256 + tid];
        sh[tid] = gelu_f(a);
    }
    __syncthreads();

    gemv_f4<64, 256>(sh, ns_w2, red, tid);
    __syncthreads();
    if (tid < 64) {
        float a = ns_b2[tid];
#pragma unroll
        for (int c = 0; c < 64; c++) a += red[c * 64 + tid];
        slg[tid] = a;
    }
    __syncthreads();
    if (tid < 64) {
        float m = -1e30f;
        for (int k = 0; k < 64; k++) m = fmaxf(m, slg[k]);
        float s = 0.f;
        for (int k = 0; k < 64; k++) s += expf(slg[k] - m);
        g_norm_w[tid] = expf(slg[tid] - m) / s;
    }

    gemv_f4<256, 1024>(sc, sv_w1, red, tid);
    __syncthreads();
    if (tid < 256) {
        float a = 0.f;
#pragma unroll
        for (int c = 0; c < 16; c++) a += red[c * 256 + tid];
        g_svctx[tid] = a;
    }
    __syncthreads();

    gemv_f4<512, 1024>(sc, nm_w1, red, tid);
    __syncthreads();
    if (tid < 512) {
        float a = 0.f;
#pragma unroll
        for (int c = 0; c < 8; c++) a += red[c * 512 + tid];
        g_basec[tid] = a;
    }
    __syncthreads();
}

// -------- k_main: persistent, group-level stealing (4 groups/block) --------
__global__ __launch_bounds__(1024, 1)
void k_main(const float* __restrict__ x, const float* __restrict__ cb,
            const float* __restrict__ proto,
            const float* __restrict__ ce_w1, const float* __restrict__ ce_b1,
            const float* __restrict__ ce_w2, const float* __restrict__ ce_b2,
            const float* __restrict__ rms_w,
            const float* __restrict__ nm_w1,
            const float* __restrict__ ns_w1, const float* __restrict__ ns_b1,
            const float* __restrict__ ns_w2, const float* __restrict__ ns_b2,
            const float* __restrict__ sv_w1)
{
    __shared__ __align__(16) float sm[5440];
    __shared__ int s_c[4][2];
    int tid = threadIdx.x;
    int blk = blockIdx.x;

    if (blk == 0) {
        run_chain(cb, ce_w1, ce_b1, ce_w2, ce_b2, rms_w, nm_w1,
                  ns_w1, ns_b1, ns_w2, ns_b2, sv_w1, sm, tid);
    } else if (blk <= 16) {
        int pi = blk - 1;
        int nt = pi & 7, ks = pi >> 3;
        gemm64(proto, nm_w1 + (size_t)2048 * 512, 512, nt, ks * 512, 512,
               g_proto_part[ks], sm);
        __syncthreads();   // all groups done with prologue before diverging
    }

    // ---- group-level stealing: each 256-thread group owns full chunks ----
    int gid = tid >> 8;          // group 0..3
    int gtid = tid & 255;        // thread-in-group: owns one float4 column
    int barid = gid + 1;         // named barriers 1..4
    const float inv_t = 1.0f / 2048.0f;

    if (gtid == 0) s_c[gid][0] = (int)atomicAdd(&g_ctr, 1u);
    bar_group(barid);
    int p = 0;
    for (;;) {
        int c = s_c[gid][p];
        if (gtid == 0) s_c[gid][p ^ 1] = (int)atomicAdd(&g_ctr, 1u);
        if (c >= NCHUNK) break;
        int b = c >> 5, s = c & 31;
        // 64 rows x 1024 cols; this thread: column quad gtid over all 64 rows
        const float4* xp = (const float4*)x
                         + ((size_t)b * 2048 + s * 64) * 256 + gtid;
        float4 a = make_float4(0.f, 0.f, 0.f, 0.f);
#pragma unroll 8
        for (int t = 0; t < 64; t++) {
            float4 v = __ldcs(xp + (size_t)t * 256);
            a.x += v.x; a.y += v.y; a.z += v.z; a.w += v.w;
        }
        a.x *= inv_t; a.y *= inv_t; a.z *= inv_t; a.w *= inv_t;
        ((float4*)g_part)[(size_t)(b * 32 + s) * 256 + gtid] = a;
        p ^= 1;
        bar_group(barid);
    }
}

// ---- k_collapse: action collapse + proto merge + resets (64 blocks) -------
__global__ __launch_bounds__(256, 4)
void k_collapse()
{
    int b = blockIdx.x, tid = threadIdx.x;
    if (tid == 0) {
        if (b == 0) g_ctr = 0u;
        g_done[b] = 0u;          // ticket reset for this replay
    }
    // action[b] = sum of 32 slabs (L2-resident)
    const float4* p = (const float4*)g_part + (size_t)b * 32 * 256 + tid;
    float4 a = make_float4(0.f, 0.f, 0.f, 0.f);
#pragma unroll 8
    for (int s = 0; s < 32; s++) {
        float4 v = p[(size_t)s * 256];
        a.x += v.x; a.y += v.y; a.z += v.z; a.w += v.w;
    }
    ((float4*)g_action)[b * 256 + tid] = a;
    // proto merge: b doubles as k index (0..63)
    if (tid < 128) {
        float4 q0 = ((const float4*)g_proto_part[0])[b * 128 + tid];
        float4 q1 = ((const float4*)g_proto_part[1])[b * 128 + tid];
        float4 q;
        q.x = q0.x + q1.x; q.y = q0.y + q1.y;
        q.z = q0.z + q1.z; q.w = q0.w + q1.w;
        ((float4*)g_proto)[b * 128 + tid] = q;
    }
}

// ---------------- k_tail: action GEMMs ------------------------------------
__global__ __launch_bounds__(256, 4)
void k_tail(const float* __restrict__ nm_w1, const float* __restrict__ sv_w1)
{
    __shared__ __align__(16) float sm[64 * 33 + 32 * 64];
    int blk = blockIdx.x;
    if (blk < 64) {
        int nt = blk & 7, ks = blk >> 3;
        gemm64(g_action, nm_w1 + (size_t)1024 * 512, 512, nt, ks * 128, 128,
               g_act_part[ks], sm);
    } else {
        int i = blk - 64;
        int nt = i & 3, ks = i >> 2;
        gemm64(g_action, sv_w1 + (size_t)1024 * 256, 256, nt, ks * 128, 128,
               g_svh_part[ks], sm);
    }
}

// ---- k_conf_final: conf blocks (0..511) + parallel sev blocks (512..575) --
// Deterministic output assembly via 9-ticket per batch (8 conf + 1 sev).
__global__ __launch_bounds__(256, 8)
void k_conf_final(const float* __restrict__ nm_b1, const float* __restrict__ nm_w2,
                  const float* __restrict__ nm_b2,
                  const float* __restrict__ sv_b1, const float* __restrict__ sv_w2,
                  const float* __restrict__ sv_b2,
                  float* __restrict__ out)
{
    __shared__ __align__(16) float s[512], w2s[512];
    __shared__ float sconf[8];
    int blk = blockIdx.x;
    int tid = threadIdx.x;

    if (blk >= 512) {
        // ---------------- severity block for batch b -----------------------
        int b = blk - 512;
        float* sred = s;
        if (tid < 64) {
            float4 a;
            {
                float4 sc = ((const float4*)g_svctx)[tid];
                float4 sb = ((const float4*)sv_b1)[tid];
                a.x = sc.x + sb.x; a.y = sc.y + sb.y;
                a.z = sc.z + sb.z; a.w = sc.w + sb.w;
            }
#pragma unroll
            for (int p = 0; p < 8; p++) {
                float4 v = *((const float4*)(g_svh_part[p] + b * 256) + tid);
                a.x += v.x; a.y += v.y; a.z += v.z; a.w += v.w;
            }
            float4 w = ((const float4*)sv_w2)[tid];
            sred[tid] = gelu_f(a.x) * w.x + gelu_f(a.y) * w.y
                      + gelu_f(a.z) * w.z + gelu_f(a.w) * w.w;
        }
        __syncthreads();
        if (tid < 32) {
            float a = sred[tid] + sred[tid + 32];
#pragma unroll
            for (int o = 16; o > 0; o >>= 1)
                a += __shfl_down_sync(0xffffffffu, a, o);
            if (tid == 0) {
                g_sev[b] = sigmoid_f(a + sv_b2[0]);
                __threadfence();
                unsigned int old = atomicAdd(&g_done[b], 1u);
                if (old == 8u) {
                    __threadfence();
                    float wc = 0.f;
#pragma unroll
                    for (int j = 0; j < 8; j++)
                        wc += ((volatile float*)g_wcp)[b * 8 + j];
                    float sev = ((volatile float*)g_sev)[b];
                    float viol = 1.0f - wc;
                    out[64 + b]  = wc;
                    out[128 + b] = viol;
                    out[192 + b] = sev;
                    out[b]       = viol * sev * 0.1f;
                }
            }
        }
        return;
    }

    // ---------------- conf block (b, kg) -----------------------------------
    int b = blk >> 3, kg = blk & 7;

    if (tid < 128) {
        float4 a;
        {
            float4 bc = ((const float4*)g_basec)[tid];
            float4 nb = ((const float4*)nm_b1)[tid];
            a.x = bc.x + nb.x; a.y = bc.y + nb.y;
            a.z = bc.z + nb.z; a.w = bc.w + nb.w;
        }
#pragma unroll
        for (int p = 0; p < 8; p++) {
            float4 v = *((const float4*)(g_act_part[p] + b * 512) + tid);
            a.x += v.x; a.y += v.y; a.z += v.z; a.w += v.w;
        }
        ((float4*)s)[tid] = a;
        ((float4*)w2s)[tid] = ((const float4*)nm_w2)[tid];
    }
    __syncthreads();

    int warp = tid >> 5, lane = tid & 31;
    int k = kg * 8 + warp;
    const float* pp = g_proto + k * 512;
    float acc0 = 0.f, acc1 = 0.f;
#pragma unroll
    for (int i = 0; i < 8; i++) {
        int h = lane + i * 32;
        int h2 = h + 256;
        acc0 += gelu_f(s[h] + pp[h]) * w2s[h];
        acc1 += gelu_f(s[h2] + pp[h2]) * w2s[h2];
    }
    float acc = acc0 + acc1;
#pragma unroll
    for (int o = 16; o > 0; o >>= 1)
        acc += __shfl_down_sync(0xffffffffu, acc, o);
    if (lane == 0) sconf[warp] = sigmoid_f(acc + nm_b2[0]) * g_norm_w[k];
    __syncthreads();

    if (tid == 0) {
        float partial = 0.f;
#pragma unroll
        for (int w = 0; w < 8; w++) partial += sconf[w];
        g_wcp[b * 8 + kg] = partial;
        __threadfence();
        unsigned int old = atomicAdd(&g_done[b], 1u);
        if (old == 8u) {
            __threadfence();
            float wc = 0.f;
#pragma unroll
            for (int j = 0; j < 8; j++)
                wc += ((volatile float*)g_wcp)[b * 8 + j];
            float sev = ((volatile float*)g_sev)[b];
            float viol = 1.0f - wc;
            out[64 + b]  = wc;
            out[128 + b] = viol;
            out[192 + b] = sev;
            out[b]       = viol * sev * 0.1f;
        }
    }
}

extern "C" void kernel_launch(void* const* d_in, const int* in_sizes, int n_in,
                              void* d_out, int out_size) {
    const float* x      = (const float*)d_in[0];
    const float* cb     = (const float*)d_in[1];
    const float* proto  = (const float*)d_in[2];
    const float* ce_w1  = (const float*)d_in[3];
    const float* ce_b1  = (const float*)d_in[4];
    const float* ce_w2  = (const float*)d_in[5];
    const float* ce_b2  = (const float*)d_in[6];
    const float* rms_w  = (const float*)d_in[7];
    const float* nm_w1  = (const float*)d_in[8];
    const float* nm_b1  = (const float*)d_in[9];
    const float* nm_w2  = (const float*)d_in[10];
    const float* nm_b2  = (const float*)d_in[11];
    const float* ns_w1  = (const float*)d_in[12];
    const float* ns_b1  = (const float*)d_in[13];
    const float* ns_w2  = (const float*)d_in[14];
    const float* ns_b2  = (const float*)d_in[15];
    const float* sv_w1  = (const float*)d_in[16];
    const float* sv_b1  = (const float*)d_in[17];
    const float* sv_w2  = (const float*)d_in[18];
    const float* sv_b2  = (const float*)d_in[19];
    float* out = (float*)d_out;

    k_main<<<148, 1024>>>(x, cb, proto, ce_w1, ce_b1, ce_w2, ce_b2, rms_w,
                          nm_w1, ns_w1, ns_b1, ns_w2, ns_b2, sv_w1);
    k_collapse<<<64, 256>>>();
    k_tail<<<96, 256>>>(nm_w1, sv_w1);
    k_conf_final<<<576, 256>>>(nm_b1, nm_w2, nm_b2, sv_b1, sv_w2, sv_b2, out);
}